// round 9
// baseline (speedup 1.0000x reference)
#include <cuda_runtime.h>
#include <cstdint>

// SNN: x[B,5] -> L1(32) -> spike(dot>=2) -> L2(32) -> L3(16) -> L4(10) -> spike.
// W1 in __constant__, read as float4 -> LDCU.128 on the uniform-const port
// (40 issues/warp instead of 160 scalar LDCU). 1 row/thread, direct x LDG,
// zero-fill + rare scatter, popc gate (sound bound, rel_err==0 in R3-R8).

__constant__ __align__(16) float cW1[160];
__device__ int g_minpop;

__global__ void setup_kernel(const float* __restrict__ W2) {
    int i = threadIdx.x;
    float mx = W2[i];
    #pragma unroll
    for (int j = 1; j < 32; j++) mx = fmaxf(mx, W2[j * 32 + i]);
    #pragma unroll
    for (int s = 16; s > 0; s >>= 1)
        mx = fmaxf(mx, __shfl_xor_sync(0xffffffffu, mx, s));
    if (i == 0) {
        int mp = 1;  // smallest popc whose bound popc*cmax could round to >= 2
        while (mp < 33 && (float)mp * mx < 1.99f) mp++;
        g_minpop = mp;
    }
}

// exact layers 2-4 (rare, ~1e-4 of rows); identical to R1-R8 validated code.
__device__ __noinline__ unsigned rare_path(unsigned mask1,
                                           const float* __restrict__ W2,
                                           const float* __restrict__ W3,
                                           const float* __restrict__ W4)
{
    unsigned mask2 = 0;
    #pragma unroll
    for (int jc = 0; jc < 32; jc += 8) {
        float acc[8] = {0, 0, 0, 0, 0, 0, 0, 0};
        unsigned mm = mask1;
        while (mm) {
            int i = __ffs(mm) - 1; mm &= mm - 1;
            #pragma unroll
            for (int j = 0; j < 8; j++) acc[j] += W2[(jc + j) * 32 + i];
        }
        #pragma unroll
        for (int j = 0; j < 8; j++)
            if (acc[j] >= 2.0f) mask2 |= 1u << (jc + j);
    }
    if (!mask2) return 0;

    unsigned mask3 = 0;
    #pragma unroll
    for (int jc = 0; jc < 16; jc += 8) {
        float acc[8] = {0, 0, 0, 0, 0, 0, 0, 0};
        unsigned mm = mask2;
        while (mm) {
            int i = __ffs(mm) - 1; mm &= mm - 1;
            #pragma unroll
            for (int j = 0; j < 8; j++) acc[j] += W3[(jc + j) * 32 + i];
        }
        #pragma unroll
        for (int j = 0; j < 8; j++)
            if (acc[j] >= 2.0f) mask3 |= 1u << (jc + j);
    }
    if (!mask3) return 0;

    float acc4[10];
    #pragma unroll
    for (int j = 0; j < 10; j++) acc4[j] = 0.0f;
    unsigned mm = mask3;
    while (mm) {
        int i = __ffs(mm) - 1; mm &= mm - 1;
        #pragma unroll
        for (int j = 0; j < 10; j++) acc4[j] += W4[j * 16 + i];
    }
    unsigned om = 0;
    #pragma unroll
    for (int j = 0; j < 10; j++)
        if (acc4[j] >= 2.0f) om |= 1u << j;
    return om;
}

#define BT 256

__global__ __launch_bounds__(BT)
void snn_kernel(const float* __restrict__ x,
                const float* __restrict__ W2,
                const float* __restrict__ W3,
                const float* __restrict__ W4,
                float* __restrict__ out)
{
    const int tid = threadIdx.x;
    const size_t row = (size_t)blockIdx.x * BT + tid;
    const int mp = g_minpop;

    // zero-fill this block's output tile: coalesced STG.128, fire-and-forget.
    {
        float4* ov = reinterpret_cast<float4*>(out + (size_t)blockIdx.x * (BT * 10));
        const float4 z = make_float4(0.f, 0.f, 0.f, 0.f);
        #pragma unroll
        for (int i = tid; i < BT * 10 / 4; i += BT) ov[i] = z;
    }

    // direct x reads
    const float* xr = x + row * 5;
    const float x0 = __ldg(xr + 0);
    const float x1 = __ldg(xr + 1);
    const float x2 = __ldg(xr + 2);
    const float x3 = __ldg(xr + 3);
    const float x4 = __ldg(xr + 4);

    __syncthreads();   // order zero-fill STGs before the rare scatter below

    // Layer 1: dense 32x5. Each chunk of 4 outputs = 20 contiguous W1 floats,
    // read as 5x LDCU.128 (uniform). Same mul->fma order as R2/R7/R8.
    unsigned mask1 = 0;
    const float4* cw4 = reinterpret_cast<const float4*>(cW1);
    #pragma unroll
    for (int c = 0; c < 8; c++) {
        float w[20];
        #pragma unroll
        for (int q = 0; q < 5; q++) {
            float4 t = cw4[c * 5 + q];          // LDCU.128
            w[q * 4 + 0] = t.x; w[q * 4 + 1] = t.y;
            w[q * 4 + 2] = t.z; w[q * 4 + 3] = t.w;
        }
        #pragma unroll
        for (int r = 0; r < 4; r++) {
            float a = w[r * 5 + 0] * x0;
            a = fmaf(w[r * 5 + 1], x1, a);
            a = fmaf(w[r * 5 + 2], x2, a);
            a = fmaf(w[r * 5 + 3], x3, a);
            a = fmaf(w[r * 5 + 4], x4, a);
            if (a >= 2.0f) mask1 |= 1u << (4 * c + r);
        }
    }

    // gate (~1e-4 taken); rare path exact
    if (__popc(mask1) >= mp) {
        unsigned om = rare_path(mask1, W2, W3, W4);
        if (om) {
            float* o = out + row * 10;
            #pragma unroll
            for (int j = 0; j < 10; j++)
                o[j] = ((om >> j) & 1u) ? 1.0f : 0.0f;
        }
    }
}

extern "C" void kernel_launch(void* const* d_in, const int* in_sizes, int n_in,
                              void* d_out, int out_size)
{
    const float* x  = (const float*)d_in[0];
    const float* W1 = (const float*)d_in[1];
    const float* W2 = (const float*)d_in[2];
    const float* W3 = (const float*)d_in[3];
    const float* W4 = (const float*)d_in[4];
    float* out = (float*)d_out;

    const int B = in_sizes[0] / 5;        // 2097152
    const int grid = B / BT;              // 8192

    cudaMemcpyToSymbolAsync(cW1, W1, 160 * sizeof(float), 0,
                            cudaMemcpyDeviceToDevice, 0);
    setup_kernel<<<1, 32>>>(W2);
    snn_kernel<<<grid, BT>>>(x, W2, W3, W4, out);
}